// round 8
// baseline (speedup 1.0000x reference)
#include <cuda_runtime.h>
#include <cstdint>
#include <cstddef>

#define T_LEN 16384
#define L_LAB 1024
#define LOG2E 1.4426950408889634f
#define LN2_D 0.6931471805599453
#define NBLK  128
#define TPB   256

// ---- persistent state (scratch; no allocations allowed) ----
__device__ unsigned long long g_pub[2][L_LAB];  // {tag<<32 | float_bits}
__device__ double g_csum;
__device__ double g_gold;

static __device__ __forceinline__ float ex2f(float x) {
    float r; asm("ex2.approx.ftz.f32 %0, %1;" : "=f"(r) : "f"(x)); return r;
}
static __device__ __forceinline__ float lg2f_(float x) {
    float r; asm("lg2.approx.f32 %0, %1;" : "=f"(r) : "f"(x)); return r;
}
static __device__ __forceinline__ unsigned long long ld_pub(const unsigned long long* p) {
    unsigned long long v;
    asm volatile("ld.relaxed.gpu.global.b64 %0, [%1];" : "=l"(v) : "l"(p));
    return v;
}
static __device__ __forceinline__ void st_pub(unsigned long long* p, unsigned long long v) {
    asm volatile("st.relaxed.gpu.global.b64 [%0], %1;" :: "l"(p), "l"(v));
}

__global__ void crf_reset() {
    int i = blockIdx.x * blockDim.x + threadIdx.x;
    if (i < 2 * L_LAB) ((unsigned long long*)g_pub)[i] = 0ull;
}

// Blocks 0..127: forward recurrence, 8 label-rows per block, one row per warp,
// W row resident in 32 registers/thread. Block 128: gold-path score.
__global__ void __launch_bounds__(TPB, 1) crf_main(const float* __restrict__ pred,
                                                   const int*   __restrict__ ref,
                                                   const float* __restrict__ trans)
{
    if (blockIdx.x == NBLK) {
        __shared__ double red[TPB];
        int tid = threadIdx.x;
        double g = 0.0;
        for (int t = tid; t < T_LEN; t += TPB) {
            int r = __ldg(&ref[t]);
            int p = (t == 0) ? (L_LAB - 2) : __ldg(&ref[t - 1]);
            g += (double)__ldg(&pred[(size_t)t * L_LAB + r])
               + (double)__ldg(&trans[(size_t)r * L_LAB + p]);
        }
        red[tid] = g; __syncthreads();
        for (int s = TPB / 2; s > 0; s >>= 1) {
            if (tid < s) red[tid] += red[tid + s];
            __syncthreads();
        }
        if (tid == 0)
            g_gold = red[0] + (double)__ldg(&trans[(size_t)(L_LAB - 1) * L_LAB + __ldg(&ref[T_LEN - 1])]);
        return;
    }

    __shared__ __align__(16) float smA[2][L_LAB];   // double-buffered stage
    const int tid = threadIdx.x;
    const int w = tid >> 5, l = tid & 31;
    const int j = blockIdx.x * 8 + w;   // this warp's output label row

    // Load W[j,:] * log2e into 32 registers. Element i = k*128 + 4*l + m -> wr[4k+m].
    float wr[32];
    {
        const float* tr = trans + (size_t)j * L_LAB;
        #pragma unroll
        for (int k = 0; k < 8; ++k) {
            float4 v = *reinterpret_cast<const float4*>(tr + k * 128 + 4 * l);
            wr[4 * k + 0] = v.x * LOG2E; wr[4 * k + 1] = v.y * LOG2E;
            wr[4 * k + 2] = v.z * LOG2E; wr[4 * k + 3] = v.w * LOG2E;
        }
    }
    // W[j, START]: i = 1022 -> k=7, lane 31, m=2 -> reg 30
    float wstart = __shfl_sync(0xffffffffu, wr[30], 31);

    // Step 1 closed form: A''(1)[j] = (W[j,START] + pred[0,j]) * log2e
    {
        float a1 = wstart + __ldg(&pred[j]) * LOG2E;
        if (l == 0)
            st_pub(&g_pub[1][j],
                   ((unsigned long long)1u << 32) | (unsigned long long)__float_as_uint(a1));
    }

    double csum = 0.0;
    float fnext = __ldg(&pred[(size_t)L_LAB + j]);   // feats for t=1

    for (int t = 1; t < T_LEN; ++t) {
        const int buf = t & 1;
        // ---- stage alpha(t): parallel tagged polls, strided layout.
        // Thread owns entries {tid, tid+256, tid+512, tid+768}: each warp-wide
        // poll load is 256 contiguous bytes (full sectors), and all pending
        // loads issue together (MLP=4) instead of 4 serial spin loops.
        {
            unsigned long long* src = g_pub[buf];
            const unsigned tag = (unsigned)t;
            float v0 = 0.f, v1 = 0.f, v2 = 0.f, v3 = 0.f;
            unsigned pending = 0xFu;
            do {
                unsigned long long e0 = 0, e1 = 0, e2 = 0, e3 = 0;
                if (pending & 1u) e0 = ld_pub(src + tid);
                if (pending & 2u) e1 = ld_pub(src + tid + 256);
                if (pending & 4u) e2 = ld_pub(src + tid + 512);
                if (pending & 8u) e3 = ld_pub(src + tid + 768);
                if ((pending & 1u) && (unsigned)(e0 >> 32) == tag) {
                    v0 = __uint_as_float((unsigned)e0); pending &= ~1u;
                }
                if ((pending & 2u) && (unsigned)(e1 >> 32) == tag) {
                    v1 = __uint_as_float((unsigned)e1); pending &= ~2u;
                }
                if ((pending & 4u) && (unsigned)(e2 >> 32) == tag) {
                    v2 = __uint_as_float((unsigned)e2); pending &= ~4u;
                }
                if ((pending & 8u) && (unsigned)(e3 >> 32) == tag) {
                    v3 = __uint_as_float((unsigned)e3); pending &= ~8u;
                }
            } while (pending);
            smA[buf][tid]       = v0;
            smA[buf][tid + 256] = v1;
            smA[buf][tid + 512] = v2;
            smA[buf][tid + 768] = v3;
        }
        __syncthreads();                 // single barrier per step
        float c = smA[buf][0];           // deterministic per-step normalizer
        if (blockIdx.x == 0 && tid == 0) csum += (double)c;

        float fcur = fnext;
        if (t + 1 < T_LEN) fnext = __ldg(&pred[(size_t)(t + 1) * L_LAB + j]);

        // ---- row j: s = sum_i exp2(A[i] + Wl[j,i]) ----
        float a0 = 0.f, a1 = 0.f, a2 = 0.f, a3 = 0.f;
        #pragma unroll
        for (int k = 0; k < 8; ++k) {
            float4 v = *reinterpret_cast<const float4*>(&smA[buf][k * 128 + 4 * l]);
            a0 += ex2f(v.x + wr[4 * k + 0]);
            a1 += ex2f(v.y + wr[4 * k + 1]);
            a2 += ex2f(v.z + wr[4 * k + 2]);
            a3 += ex2f(v.w + wr[4 * k + 3]);
        }
        float s = (a0 + a1) + (a2 + a3);
        #pragma unroll
        for (int o = 16; o > 0; o >>= 1) s += __shfl_xor_sync(0xffffffffu, s, o);

        if (l == 0) {
            float an = lg2f_(s) - c + fcur * LOG2E;
            st_pub(&g_pub[(t + 1) & 1][j],
                   ((unsigned long long)(unsigned)(t + 1) << 32)
                   | (unsigned long long)__float_as_uint(an));
        }
        // no trailing barrier: next iteration stages into the other smA buffer,
        // and threads can be at most one barrier apart, so the earliest a buffer
        // is re-staged is after every thread passed the barrier that follows its
        // last read of that buffer.
    }

    if (blockIdx.x == 0 && tid == 0) g_csum = csum;
}

// Terminal: forward = LSE_j(A''(T)[j] + Wl[STOP,j]) + Csum (max-stabilized: the
// STOP row is uniformly -1e4, so without the max everything underflows).
__global__ void crf_final(const float* __restrict__ trans, float* __restrict__ out)
{
    __shared__ float  sm[TPB];
    __shared__ double sd[TPB];
    int tid = threadIdx.x;

    float x[4];
    float m = -3.4e38f;
    #pragma unroll
    for (int q = 0; q < 4; ++q) {
        int jj = q * TPB + tid;
        float a  = __uint_as_float((unsigned)(g_pub[T_LEN & 1][jj] & 0xffffffffull));
        float wl = __ldg(&trans[(size_t)(L_LAB - 1) * L_LAB + jj]) * LOG2E;
        x[q] = a + wl;
        m = fmaxf(m, x[q]);
    }
    sm[tid] = m; __syncthreads();
    for (int s = TPB / 2; s > 0; s >>= 1) {
        if (tid < s) sm[tid] = fmaxf(sm[tid], sm[tid + s]);
        __syncthreads();
    }
    float M = sm[0];

    double loc = 0.0;
    #pragma unroll
    for (int q = 0; q < 4; ++q) loc += (double)ex2f(x[q] - M);
    sd[tid] = loc; __syncthreads();
    for (int s = TPB / 2; s > 0; s >>= 1) {
        if (tid < s) sd[tid] += sd[tid + s];
        __syncthreads();
    }
    if (tid == 0) {
        double fwd = (log2(sd[0]) + (double)M + g_csum) * LN2_D;
        out[0] = (float)(fwd - g_gold);
    }
}

extern "C" void kernel_launch(void* const* d_in, const int* in_sizes, int n_in,
                              void* d_out, int out_size)
{
    const float* pred = nullptr;
    const int*   ref  = nullptr;
    const float* trans = nullptr;
    for (int i = 0; i < n_in; ++i) {
        if (in_sizes[i] == T_LEN)                 ref   = (const int*)d_in[i];
        else if (in_sizes[i] == L_LAB * L_LAB)    trans = (const float*)d_in[i];
        else if (in_sizes[i] == T_LEN * L_LAB)    pred  = (const float*)d_in[i];
    }
    crf_reset<<<8, 256>>>();
    crf_main<<<NBLK + 1, TPB>>>(pred, ref, trans);
    crf_final<<<1, TPB>>>(trans, (float*)d_out);
}